// round 16
// baseline (speedup 1.0000x reference)
#include <cuda_runtime.h>
#include <cuda_bf16.h>
#include <math.h>
#include <stdint.h>

#define B_TOT 65536
// H=64, HC=128, N=8, OBS0=6, OBS1=1024, OBS2=7, NA=2

typedef unsigned long long u64;
typedef unsigned short u16;
typedef unsigned int u32;

// ---------------------------------------------------------------------------
// helpers
// ---------------------------------------------------------------------------
static __device__ __forceinline__ uint32_t smem_u32(const void* p) {
    uint32_t a;
    asm("{ .reg .u64 t; cvta.to.shared.u64 t, %1; cvt.u32.u64 %0, t; }"
        : "=r"(a) : "l"(p));
    return a;
}
static __device__ __forceinline__ void mma16816(float* c, const u32* a, const u32* b) {
    asm volatile(
        "mma.sync.aligned.m16n8k16.row.col.f32.bf16.bf16.f32 "
        "{%0,%1,%2,%3}, {%4,%5,%6,%7}, {%8,%9}, {%0,%1,%2,%3};"
        : "+f"(c[0]), "+f"(c[1]), "+f"(c[2]), "+f"(c[3])
        : "r"(a[0]), "r"(a[1]), "r"(a[2]), "r"(a[3]), "r"(b[0]), "r"(b[1]));
}
static __device__ __forceinline__ void ldsm4(u32& r0, u32& r1, u32& r2, u32& r3, u32 a) {
    asm volatile("ldmatrix.sync.aligned.m8n8.x4.shared.b16 {%0,%1,%2,%3}, [%4];"
                 : "=r"(r0), "=r"(r1), "=r"(r2), "=r"(r3) : "r"(a));
}
static __device__ __forceinline__ void ldsm4t(u32& r0, u32& r1, u32& r2, u32& r3, u32 a) {
    asm volatile("ldmatrix.sync.aligned.m8n8.x4.trans.shared.b16 {%0,%1,%2,%3}, [%4];"
                 : "=r"(r0), "=r"(r1), "=r"(r2), "=r"(r3) : "r"(a));
}
// exact pair split: h2 = {x0>>16, x1>>16}; l2 = bf16rn(residuals)
static __device__ __forceinline__ void split2(float x0, float x1, u32& h2, u32& l2) {
    u32 b0 = __float_as_uint(x0), b1 = __float_as_uint(x1);
    asm("prmt.b32 %0, %1, %2, 0x7632;" : "=r"(h2) : "r"(b0), "r"(b1));
    float r0 = x0 - __uint_as_float(b0 & 0xffff0000u);
    float r1 = x1 - __uint_as_float(b1 & 0xffff0000u);
    asm("cvt.rn.bf16x2.f32 %0, %1, %2;" : "=r"(l2) : "f"(r1), "f"(r0));
}
#define CP_A16(d, s) \
    asm volatile("cp.async.ca.shared.global [%0], [%1], 16;" :: "r"(d), "l"(s) : "memory")
#define CP_COMMIT() asm volatile("cp.async.commit_group;" ::: "memory")
#define CP_WAIT0()  asm volatile("cp.async.wait_group 0;" ::: "memory")

// ---------------------------------------------------------------------------
// Scratch (static device globals: allocation-free)
// ---------------------------------------------------------------------------
__device__ float g_concat[(size_t)B_TOT * 192];
// pre-split weights, [k][n] row-major bf16
__device__ u16 g_Wgh[1024 * 64],  g_Wgl[1024 * 64];
__device__ u16 g_Wc1h[192 * 128], g_Wc1l[192 * 128];
__device__ u16 g_Wc2h[128 * 128], g_Wc2l[128 * 128];
__device__ u16 g_Ws2h[64 * 64],   g_Ws2l[64 * 64];
__device__ u16 g_Mh[64 * 64],     g_Ml[64 * 64];      // Wq@Wk^T split
__device__ u16 g_Wvh[64 * 64],    g_Wvl[64 * 64];

// ---------------------------------------------------------------------------
// K0: split all weights into bf16 hi/lo; also computes M = Wq@Wk^T (split)
// 2 elements/thread (MLP=2, latency-bound kernel)
// ---------------------------------------------------------------------------
__global__ void k_split(const float* __restrict__ Wg, const float* __restrict__ Wc1,
                        const float* __restrict__ Wc2, const float* __restrict__ Ws2,
                        const float* __restrict__ Wv,
                        const float* __restrict__ Wq, const float* __restrict__ Wk) {
    const int base = (blockIdx.x * 256 + threadIdx.x) * 2;
#pragma unroll
    for (int j = 0; j < 2; j++) {
        int i = base + j;
        float x;
        u16 *dh, *dl; int off;
        if (i < 65536)       { x = Wg[i];           dh = g_Wgh;  dl = g_Wgl;  off = i; }
        else if (i < 90112)  { off = i - 65536;  x = Wc1[off]; dh = g_Wc1h; dl = g_Wc1l; }
        else if (i < 106496) { off = i - 90112;  x = Wc2[off]; dh = g_Wc2h; dl = g_Wc2l; }
        else if (i < 110592) { off = i - 106496; x = Ws2[off]; dh = g_Ws2h; dl = g_Ws2l; }
        else if (i < 114688) { off = i - 110592; x = Wv[off];  dh = g_Wvh;  dl = g_Wvl; }
        else if (i < 118784) {
            off = i - 114688;
            int r = off >> 6, jj = off & 63;
            float s = 0.f;
#pragma unroll
            for (int h = 0; h < 64; h++) s = fmaf(Wq[r * 64 + h], Wk[jj * 64 + h], s);
            x = s; dh = g_Mh; dl = g_Ml;
        } else continue;
        __nv_bfloat16 hb = __float2bfloat16(x);
        __nv_bfloat16 lb = __float2bfloat16(x - __bfloat162float(hb));
        dh[off] = __bfloat16_as_ushort(hb);
        dl[off] = __bfloat16_as_ushort(lb);
    }
}

// ---------------------------------------------------------------------------
// K1 v3 (round-13 champion, exact): env_e = relu(S1 @ Wg + bg)
// 64-row tiles, grid 1024, 3 CTAs/SM. B via cp.async. Warp tile 32x16 (2m x 4n).
// smem: Ah@0 Al@9216 Bh@18432 Bl@27648 bias@36864  (37.1 KB)
// ---------------------------------------------------------------------------
#define K1_SMEM_BYTES (36864 + 256)

__global__ __launch_bounds__(256, 3)
void k1_gemm(const float* __restrict__ A, const float* __restrict__ bias,
             float* __restrict__ C) {
    extern __shared__ char smem[];
    const u32 sbase = smem_u32(smem);
    const u32 ah_b = sbase, al_b = sbase + 9216;
    const u32 bh_b = sbase + 18432, bl_b = sbase + 27648;
    float* bs = (float*)(smem + 36864);

    const int tid = threadIdx.x;
    const int wid = tid >> 5, lane = tid & 31;
    const int row0 = blockIdx.x * 64;
    const int mwarp = wid >> 2, nwarp = wid & 3;
    const int g = lane >> 2, t = lane & 3;
    const int lr = lane & 15, lc = (lane >> 4) << 3;
    const int mrow0 = mwarp * 32, ncol0 = nwarp * 16;

    if (tid < 64) bs[tid] = bias[tid];

    float acc[2][2][4];
#pragma unroll
    for (int mt = 0; mt < 2; mt++)
#pragma unroll
        for (int nt = 0; nt < 2; nt++)
#pragma unroll
            for (int r = 0; r < 4; r++) acc[mt][nt][r] = 0.f;

    for (int c = 0; c < 16; c++) {
        const int k0 = c * 64;
        {   // B tiles via cp.async (overlapped by A convert)
            const int kk = tid >> 2, cg = (tid & 3) * 16;
            const u16* sh = g_Wgh + (size_t)(k0 + kk) * 64 + cg;
            const u16* sl = g_Wgl + (size_t)(k0 + kk) * 64 + cg;
            u32 dh = bh_b + kk * 144 + cg * 2;
            u32 dl = bl_b + kk * 144 + cg * 2;
            CP_A16(dh, sh);      CP_A16(dh + 16, sh + 8);
            CP_A16(dl, sl);      CP_A16(dl + 16, sl + 8);
            CP_COMMIT();
        }
        {   // A chunk [64 x 64] fp32 -> split bf16 (4 float4/thread)
            const int m = tid >> 2, cq = tid & 3;
            const float* src = A + (size_t)(row0 + m) * 1024 + k0 + cq * 16;
            char* dh = smem + m * 144 + cq * 32;
            char* dl = smem + 9216 + m * 144 + cq * 32;
#pragma unroll
            for (int q = 0; q < 4; q++) {
                float4 v = *reinterpret_cast<const float4*>(src + q * 4);
                uint2 hh, ll;
                split2(v.x, v.y, hh.x, ll.x);
                split2(v.z, v.w, hh.y, ll.y);
                *reinterpret_cast<uint2*>(dh + q * 8) = hh;
                *reinterpret_cast<uint2*>(dl + q * 8) = ll;
            }
        }
        CP_WAIT0();
        __syncthreads();

#pragma unroll
        for (int k16 = 0; k16 < 4; k16++) {
            const int kk = k16 * 16;
            u32 bh[4], bl[4];
            ldsm4t(bh[0], bh[1], bh[2], bh[3], bh_b + ((kk + lr) * 72 + ncol0 + lc) * 2);
            ldsm4t(bl[0], bl[1], bl[2], bl[3], bl_b + ((kk + lr) * 72 + ncol0 + lc) * 2);
#pragma unroll
            for (int mt = 0; mt < 2; mt++) {
                u32 ah[4], al[4];
                ldsm4(ah[0], ah[1], ah[2], ah[3],
                      ah_b + ((mrow0 + mt * 16 + lr) * 72 + kk + lc) * 2);
                ldsm4(al[0], al[1], al[2], al[3],
                      al_b + ((mrow0 + mt * 16 + lr) * 72 + kk + lc) * 2);
#pragma unroll
                for (int nt = 0; nt < 2; nt++) {
                    mma16816(acc[mt][nt], ah, &bh[nt * 2]);
                    mma16816(acc[mt][nt], ah, &bl[nt * 2]);
                    mma16816(acc[mt][nt], al, &bh[nt * 2]);
                }
            }
        }
        __syncthreads();
    }

#pragma unroll
    for (int mt = 0; mt < 2; mt++) {
#pragma unroll
        for (int nt = 0; nt < 2; nt++) {
            int r = row0 + mrow0 + mt * 16 + g;
            int cl = ncol0 + nt * 8 + t * 2;
            float b0v = bs[cl], b1v = bs[cl + 1];
            float2 v0, v1;
            v0.x = fmaxf(acc[mt][nt][0] + b0v, 0.f);
            v0.y = fmaxf(acc[mt][nt][1] + b1v, 0.f);
            v1.x = fmaxf(acc[mt][nt][2] + b0v, 0.f);
            v1.y = fmaxf(acc[mt][nt][3] + b1v, 0.f);
            *reinterpret_cast<float2*>(C + (size_t)r * 192 + 64 + cl) = v0;
            *reinterpret_cast<float2*>(C + (size_t)(r + 8) * 192 + 64 + cl) = v1;
        }
    }
}

// ---------------------------------------------------------------------------
// K2 v5: fused attention (round-13, unchanged)
// ---------------------------------------------------------------------------
#define AT_E1H   0
#define AT_E1L   18432
#define AT_E2    0
#define AT_WS2H  36864
#define AT_WS2L  46080
#define AT_MH    55296
#define AT_ML    64512
#define AT_WVH   73728
#define AT_WVL   82944
#define AT_OWNH  92160
#define AT_OWNL  94464
#define AT_TT    96768
#define AT_W0    101120
#define AT_WS1   102656
#define AT_B0    104448
#define AT_BS1   104704
#define AT_BS2   104960
#define AT_SC    105216
#define AT_AL    105728
#define AT_MK    106240
#define ATTN_SMEM_BYTES 106752

__global__ __launch_bounds__(256, 2)
void k_attn5(const float* __restrict__ S0, const float* __restrict__ S2,
             const float* __restrict__ W0, const float* __restrict__ b0,
             const float* __restrict__ Ws1, const float* __restrict__ bs1,
             const float* __restrict__ bs2) {
    extern __shared__ char smem[];
    float* E2   = (float*)(smem + AT_E2);
    float* tt   = (float*)(smem + AT_TT);
    float* W0s  = (float*)(smem + AT_W0);
    float* Ws1s = (float*)(smem + AT_WS1);
    float* b0s  = (float*)(smem + AT_B0);
    float* bs1s = (float*)(smem + AT_BS1);
    float* bs2s = (float*)(smem + AT_BS2);
    float* sc   = (float*)(smem + AT_SC);
    float* al   = (float*)(smem + AT_AL);
    float* mk   = (float*)(smem + AT_MK);
    const u32 sbase = smem_u32(smem);
    const u32 e1h_b = sbase + AT_E1H, e1l_b = sbase + AT_E1L;
    const u32 wsh_b = sbase + AT_WS2H, wsl_b = sbase + AT_WS2L;
    const u32 mh_b  = sbase + AT_MH,   ml_b  = sbase + AT_ML;
    const u32 wvh_b = sbase + AT_WVH,  wvl_b = sbase + AT_WVL;
    const u32 ownh_b = sbase + AT_OWNH, ownl_b = sbase + AT_OWNL;

    const int tid = threadIdx.x;
    const int wid = tid >> 5, lane = tid & 31;
    const int gb0 = blockIdx.x * 16;

    if (tid < 96)  reinterpret_cast<float4*>(W0s)[tid]  =
        reinterpret_cast<const float4*>(W0)[tid];
    if (tid >= 96 && tid < 208) reinterpret_cast<float4*>(Ws1s)[tid - 96] =
        reinterpret_cast<const float4*>(Ws1)[tid - 96];
    if (tid >= 208 && tid < 224) reinterpret_cast<float4*>(b0s)[tid - 208] =
        reinterpret_cast<const float4*>(b0)[tid - 208];
    if (tid >= 224 && tid < 240) reinterpret_cast<float4*>(bs1s)[tid - 224] =
        reinterpret_cast<const float4*>(bs1)[tid - 224];
    if (tid >= 240) reinterpret_cast<float4*>(bs2s)[tid - 240] =
        reinterpret_cast<const float4*>(bs2)[tid - 240];
    {
        const int kk = tid >> 2, cg = (tid & 3) * 16;
        const int go = kk * 64 + cg;
        const int so = kk * 144 + cg * 2;
        const u16* srcs[6] = {g_Ws2h, g_Ws2l, g_Mh, g_Ml, g_Wvh, g_Wvl};
        const int offs[6] = {AT_WS2H, AT_WS2L, AT_MH, AT_ML, AT_WVH, AT_WVL};
#pragma unroll
        for (int a = 0; a < 6; a++) {
            char* d = smem + offs[a] + so;
            *reinterpret_cast<uint4*>(d)      = *reinterpret_cast<const uint4*>(srcs[a] + go);
            *reinterpret_cast<uint4*>(d + 16) = *reinterpret_cast<const uint4*>(srcs[a] + go + 8);
        }
    }

    // P1: own_e
    {
        const int row = tid >> 4, c0 = (tid & 15) * 4;
        const float* s0 = S0 + (size_t)(gb0 + row) * 6;
        float x0 = s0[0], x1 = s0[1], x2 = s0[2], x3 = s0[3], x4 = s0[4], x5 = s0[5];
        float* og = g_concat + (size_t)(gb0 + row) * 192;
        __syncthreads();
        float4 a4 = *reinterpret_cast<const float4*>(b0s + c0);
#pragma unroll
        for (int kk = 0; kk < 6; kk++) {
            float xv = (kk == 0) ? x0 : (kk == 1) ? x1 : (kk == 2) ? x2 :
                       (kk == 3) ? x3 : (kk == 4) ? x4 : x5;
            float4 w4 = *reinterpret_cast<const float4*>(W0s + kk * 64 + c0);
            a4.x = fmaf(xv, w4.x, a4.x); a4.y = fmaf(xv, w4.y, a4.y);
            a4.z = fmaf(xv, w4.z, a4.z); a4.w = fmaf(xv, w4.w, a4.w);
        }
        a4.x = fmaxf(a4.x, 0.f); a4.y = fmaxf(a4.y, 0.f);
        a4.z = fmaxf(a4.z, 0.f); a4.w = fmaxf(a4.w, 0.f);
        uint2 hh, ll;
        split2(a4.x, a4.y, hh.x, ll.x);
        split2(a4.z, a4.w, hh.y, ll.y);
        *reinterpret_cast<uint2*>(smem + AT_OWNH + row * 144 + c0 * 2) = hh;
        *reinterpret_cast<uint2*>(smem + AT_OWNL + row * 144 + c0 * 2) = ll;
        *reinterpret_cast<float4*>(og + c0) = a4;
    }

    // P2: E1
    {
        const int rr = tid >> 1, h = tid & 1, j0 = h * 32;
        const float* s2 = S2 + ((size_t)gb0 * 8 + rr) * 7;
        float y0 = s2[0], y1 = s2[1], y2 = s2[2], y3 = s2[3], y4 = s2[4], y5 = s2[5], y6 = s2[6];
        if (h == 0)
            mk[rr] = ((y0 + y1 + y2 + y3 + y4 + y5 + y6) != 0.f) ? 1.f : 0.f;
        float a[32];
#pragma unroll
        for (int q = 0; q < 8; q++) {
            float4 v4 = *reinterpret_cast<const float4*>(bs1s + j0 + q * 4);
            a[q * 4 + 0] = v4.x; a[q * 4 + 1] = v4.y;
            a[q * 4 + 2] = v4.z; a[q * 4 + 3] = v4.w;
        }
#pragma unroll
        for (int kk = 0; kk < 7; kk++) {
            float yv = (kk == 0) ? y0 : (kk == 1) ? y1 : (kk == 2) ? y2 :
                       (kk == 3) ? y3 : (kk == 4) ? y4 : (kk == 5) ? y5 : y6;
#pragma unroll
            for (int q = 0; q < 8; q++) {
                float4 w4 = *reinterpret_cast<const float4*>(Ws1s + kk * 64 + j0 + q * 4);
                a[q * 4 + 0] = fmaf(yv, w4.x, a[q * 4 + 0]);
                a[q * 4 + 1] = fmaf(yv, w4.y, a[q * 4 + 1]);
                a[q * 4 + 2] = fmaf(yv, w4.z, a[q * 4 + 2]);
                a[q * 4 + 3] = fmaf(yv, w4.w, a[q * 4 + 3]);
            }
        }
#pragma unroll
        for (int j = 0; j < 32; j++) a[j] = fmaxf(a[j], 0.f);
        char* dh = smem + AT_E1H + rr * 144 + j0 * 2;
        char* dl = smem + AT_E1L + rr * 144 + j0 * 2;
#pragma unroll
        for (int q = 0; q < 32; q += 8) {
            uint4 vh, vl;
            split2(a[q + 0], a[q + 1], vh.x, vl.x);
            split2(a[q + 2], a[q + 3], vh.y, vl.y);
            split2(a[q + 4], a[q + 5], vh.z, vl.z);
            split2(a[q + 6], a[q + 7], vh.w, vl.w);
            *reinterpret_cast<uint4*>(dh + q * 2) = vh;
            *reinterpret_cast<uint4*>(dl + q * 2) = vl;
        }
    }
    __syncthreads();

    // P3: E2 = relu(E1 @ Ws2 + bs2) via HMMA
    float acc[2][4][4];
    {
        const int mwarp = wid >> 1, nwarp = wid & 1;
        const int lr = lane & 15, lc = (lane >> 4) << 3;
        const int mrow0 = mwarp * 32, ncol0 = nwarp * 32;
#pragma unroll
        for (int mt = 0; mt < 2; mt++)
#pragma unroll
            for (int nt = 0; nt < 4; nt++)
#pragma unroll
                for (int r = 0; r < 4; r++) acc[mt][nt][r] = 0.f;

#pragma unroll
        for (int k16 = 0; k16 < 4; k16++) {
            const int kk = k16 * 16;
            u32 bh[8], bl[8];
            ldsm4t(bh[0], bh[1], bh[2], bh[3], wsh_b + ((kk + lr) * 72 + ncol0 + lc) * 2);
            ldsm4t(bh[4], bh[5], bh[6], bh[7], wsh_b + ((kk + lr) * 72 + ncol0 + 16 + lc) * 2);
            ldsm4t(bl[0], bl[1], bl[2], bl[3], wsl_b + ((kk + lr) * 72 + ncol0 + lc) * 2);
            ldsm4t(bl[4], bl[5], bl[6], bl[7], wsl_b + ((kk + lr) * 72 + ncol0 + 16 + lc) * 2);
#pragma unroll
            for (int mt = 0; mt < 2; mt++) {
                u32 ah[4], alr[4];
                ldsm4(ah[0], ah[1], ah[2], ah[3],
                      e1h_b + ((mrow0 + mt * 16 + lr) * 72 + kk + lc) * 2);
                ldsm4(alr[0], alr[1], alr[2], alr[3],
                      e1l_b + ((mrow0 + mt * 16 + lr) * 72 + kk + lc) * 2);
#pragma unroll
                for (int nt = 0; nt < 4; nt++) {
                    mma16816(acc[mt][nt], ah, &bh[nt * 2]);
                    mma16816(acc[mt][nt], ah, &bl[nt * 2]);
                    mma16816(acc[mt][nt], alr, &bh[nt * 2]);
                }
            }
        }
    }
    __syncthreads();

    // E2 epilogue + P4 (own@M HMMA)
    {
        const int mwarp = wid >> 1, nwarp = wid & 1;
        const int g = lane >> 2, t = lane & 3;
        const int mrow0 = mwarp * 32, ncol0 = nwarp * 32;
#pragma unroll
        for (int mt = 0; mt < 2; mt++) {
#pragma unroll
            for (int nt = 0; nt < 4; nt++) {
                int r = mrow0 + mt * 16 + g;
                int cl = ncol0 + nt * 8 + t * 2;
                float b0v = bs2s[cl], b1v = bs2s[cl + 1];
                float2 v0, v1;
                v0.x = fmaxf(acc[mt][nt][0] + b0v, 0.f);
                v0.y = fmaxf(acc[mt][nt][1] + b1v, 0.f);
                v1.x = fmaxf(acc[mt][nt][2] + b0v, 0.f);
                v1.y = fmaxf(acc[mt][nt][3] + b1v, 0.f);
                *reinterpret_cast<float2*>(E2 + r * 68 + cl) = v0;
                *reinterpret_cast<float2*>(E2 + (r + 8) * 68 + cl) = v1;
            }
        }
    }
    if (wid < 4) {
        const int ncol0 = wid * 16;
        const int lr = lane & 15, lc = (lane >> 4) << 3;
        float tac[2][4];
#pragma unroll
        for (int nt = 0; nt < 2; nt++)
#pragma unroll
            for (int r = 0; r < 4; r++) tac[nt][r] = 0.f;
#pragma unroll
        for (int k16 = 0; k16 < 4; k16++) {
            const int kk = k16 * 16;
            u32 bh[4], bl[4], ah[4], alr[4];
            ldsm4t(bh[0], bh[1], bh[2], bh[3], mh_b + ((kk + lr) * 72 + ncol0 + lc) * 2);
            ldsm4t(bl[0], bl[1], bl[2], bl[3], ml_b + ((kk + lr) * 72 + ncol0 + lc) * 2);
            ldsm4(ah[0], ah[1], ah[2], ah[3], ownh_b + lr * 144 + (kk + lc) * 2);
            ldsm4(alr[0], alr[1], alr[2], alr[3], ownl_b + lr * 144 + (kk + lc) * 2);
#pragma unroll
            for (int nt = 0; nt < 2; nt++) {
                mma16816(tac[nt], ah, &bh[nt * 2]);
                mma16816(tac[nt], ah, &bl[nt * 2]);
                mma16816(tac[nt], alr, &bh[nt * 2]);
            }
        }
        const int g = lane >> 2, tq = lane & 3;
#pragma unroll
        for (int nt = 0; nt < 2; nt++) {
            int cl = ncol0 + nt * 8 + tq * 2;
            *reinterpret_cast<float2*>(tt + g * 68 + cl) =
                make_float2(tac[nt][0], tac[nt][1]);
            *reinterpret_cast<float2*>(tt + (g + 8) * 68 + cl) =
                make_float2(tac[nt][2], tac[nt][3]);
        }
    }
    __syncthreads();

    // P5: scores
    {
        const int rr = tid >> 1, h = tid & 1, k0 = h * 32;
        const int lb = rr >> 3;
        float s = 0.f;
#pragma unroll
        for (int k = 0; k < 32; k += 4) {
            float4 t4 = *reinterpret_cast<const float4*>(tt + lb * 68 + k0 + k);
            float4 e4 = *reinterpret_cast<const float4*>(E2 + rr * 68 + k0 + k);
            s = fmaf(t4.x, e4.x, s); s = fmaf(t4.y, e4.y, s);
            s = fmaf(t4.z, e4.z, s); s = fmaf(t4.w, e4.w, s);
        }
        s += __shfl_xor_sync(0xffffffffu, s, 1);
        if (h == 0)
            sc[rr] = (mk[rr] != 0.f) ? (s * 0.125f) : __int_as_float(0xff800000);
    }
    __syncthreads();

    // P6: softmax
    if (tid < 16) {
        float m = __int_as_float(0xff800000);
#pragma unroll
        for (int n = 0; n < 8; n++) m = fmaxf(m, sc[tid * 8 + n]);
        float e[8]; float ssum = 0.f;
#pragma unroll
        for (int n = 0; n < 8; n++) { float v = expf(sc[tid * 8 + n] - m); e[n] = v; ssum += v; }
        float inv = 1.f / ssum;
#pragma unroll
        for (int n = 0; n < 8; n++) al[tid * 8 + n] = e[n] * inv;
    }
    __syncthreads();

    // P7a: wsum -> split bf16 (aliases own buffers)
    {
        const int row = tid >> 4, c0 = (tid & 15) * 4;
        float4 a4 = {0.f, 0.f, 0.f, 0.f};
#pragma unroll
        for (int n = 0; n < 8; n++) {
            float av = al[row * 8 + n];
            float4 e4 = *reinterpret_cast<const float4*>(E2 + (row * 8 + n) * 68 + c0);
            a4.x = fmaf(av, e4.x, a4.x); a4.y = fmaf(av, e4.y, a4.y);
            a4.z = fmaf(av, e4.z, a4.z); a4.w = fmaf(av, e4.w, a4.w);
        }
        uint2 hh, ll;
        split2(a4.x, a4.y, hh.x, ll.x);
        split2(a4.z, a4.w, hh.y, ll.y);
        *reinterpret_cast<uint2*>(smem + AT_OWNH + row * 144 + c0 * 2) = hh;
        *reinterpret_cast<uint2*>(smem + AT_OWNL + row * 144 + c0 * 2) = ll;
    }
    __syncthreads();

    // P7b: v_att = wsum @ Wv via HMMA
    if (wid < 4) {
        const int ncol0 = wid * 16;
        const int lr = lane & 15, lc = (lane >> 4) << 3;
        float vac[2][4];
#pragma unroll
        for (int nt = 0; nt < 2; nt++)
#pragma unroll
            for (int r = 0; r < 4; r++) vac[nt][r] = 0.f;
#pragma unroll
        for (int k16 = 0; k16 < 4; k16++) {
            const int kk = k16 * 16;
            u32 bh[4], bl[4], ah[4], alr[4];
            ldsm4t(bh[0], bh[1], bh[2], bh[3], wvh_b + ((kk + lr) * 72 + ncol0 + lc) * 2);
            ldsm4t(bl[0], bl[1], bl[2], bl[3], wvl_b + ((kk + lr) * 72 + ncol0 + lc) * 2);
            ldsm4(ah[0], ah[1], ah[2], ah[3], ownh_b + lr * 144 + (kk + lc) * 2);
            ldsm4(alr[0], alr[1], alr[2], alr[3], ownl_b + lr * 144 + (kk + lc) * 2);
#pragma unroll
            for (int nt = 0; nt < 2; nt++) {
                mma16816(vac[nt], ah, &bh[nt * 2]);
                mma16816(vac[nt], ah, &bl[nt * 2]);
                mma16816(vac[nt], alr, &bh[nt * 2]);
            }
        }
        const int g = lane >> 2, tq = lane & 3;
#pragma unroll
        for (int nt = 0; nt < 2; nt++) {
            int cl = ncol0 + nt * 8 + tq * 2;
            *reinterpret_cast<float2*>(g_concat + (size_t)(gb0 + g) * 192 + 128 + cl) =
                make_float2(vac[nt][0], vac[nt][1]);
            *reinterpret_cast<float2*>(g_concat + (size_t)(gb0 + g + 8) * 192 + 128 + cl) =
                make_float2(vac[nt][2], vac[nt][3]);
        }
    }
}

// ---------------------------------------------------------------------------
// K3: fused tail (round-13, unchanged)
// ---------------------------------------------------------------------------
#define TL_AH   0
#define TL_AL   9216
#define TL_BH   18432
#define TL_BL   35840
#define TL_H1H  0
#define TL_H1L  17408
#define TL_B2H  53248
#define TL_B2L  70656
#define TL_W3   88064
#define TL_BC1  89088
#define TL_BC2  89600
#define TL_PT   90112
#define TAIL_SMEM_BYTES 92160

static __device__ __forceinline__ void tail_cpB(u32 sbase, int offH, int offL,
                                                const u16* gh, const u16* gl, int k0) {
    const int tid = threadIdx.x;
    const int kk = tid >> 2, cq = tid & 3;
    const u16* sh = gh + (size_t)(k0 + kk) * 128 + cq * 32;
    const u16* sl = gl + (size_t)(k0 + kk) * 128 + cq * 32;
    u32 dh = sbase + offH + kk * 272 + cq * 64;
    u32 dl = sbase + offL + kk * 272 + cq * 64;
#pragma unroll
    for (int q = 0; q < 4; q++) {
        CP_A16(dh + q * 16, sh + q * 8);
        CP_A16(dl + q * 16, sl + q * 8);
    }
}

__global__ __launch_bounds__(256, 2)
void k_tail(const float* __restrict__ bc1, const float* __restrict__ bc2,
            const float* __restrict__ Wc3, const float* __restrict__ bc3,
            float* __restrict__ out) {
    extern __shared__ char smem[];
    const u32 sbase = smem_u32(smem);
    float* W3s = (float*)(smem + TL_W3);
    float* b1s = (float*)(smem + TL_BC1);
    float* b2s = (float*)(smem + TL_BC2);
    float* pt  = (float*)(smem + TL_PT);
    __shared__ float b3s[2];

    const int tid = threadIdx.x;
    const int wid = tid >> 5, lane = tid & 31;
    const int row0 = blockIdx.x * 64;
    const int mwarp = wid >> 2, nwarp = wid & 3;
    const int g = lane >> 2, t = lane & 3;
    const int lr = lane & 15, lc = (lane >> 4) << 3;
    const int mrow0 = mwarp * 32, ncol0 = nwarp * 32;

    if (tid < 128) b1s[tid] = bc1[tid];
    else b2s[tid - 128] = bc2[tid - 128];
    if (tid < 64) reinterpret_cast<float4*>(W3s)[tid] =
        reinterpret_cast<const float4*>(Wc3)[tid];
    if (tid == 0) { b3s[0] = bc3[0]; b3s[1] = bc3[1]; }

    tail_cpB(sbase, TL_B2H, TL_B2L, g_Wc2h, g_Wc2l, 0);
    CP_COMMIT();

    float acc[2][4][4];
#pragma unroll
    for (int mt = 0; mt < 2; mt++)
#pragma unroll
        for (int nt = 0; nt < 4; nt++)
#pragma unroll
            for (int r = 0; r < 4; r++) acc[mt][nt][r] = 0.f;

    // ---- Phase 1: h1 = relu(concat @ Wc1 + bc1), K = 192 ----
    for (int c = 0; c < 3; c++) {
        const int k0 = c * 64;
        tail_cpB(sbase, TL_BH, TL_BL, g_Wc1h, g_Wc1l, k0);
        CP_COMMIT();
        {
            const int m = tid >> 2, cq = tid & 3;
            const float* src = g_concat + (size_t)(row0 + m) * 192 + k0 + cq * 16;
            char* dh = smem + TL_AH + m * 144 + cq * 32;
            char* dl = smem + TL_AL + m * 144 + cq * 32;
#pragma unroll
            for (int q = 0; q < 4; q++) {
                float4 v = *reinterpret_cast<const float4*>(src + q * 4);
                uint2 hh, ll;
                split2(v.x, v.y, hh.x, ll.x);
                split2(v.z, v.w, hh.y, ll.y);
                *reinterpret_cast<uint2*>(dh + q * 8) = hh;
                *reinterpret_cast<uint2*>(dl + q * 8) = ll;
            }
        }
        CP_WAIT0();
        __syncthreads();
#pragma unroll
        for (int k16 = 0; k16 < 4; k16++) {
            const int kk = k16 * 16;
            u32 bh[8], bl[8];
            ldsm4t(bh[0], bh[1], bh[2], bh[3],
                   sbase + TL_BH + ((kk + lr) * 136 + ncol0 + lc) * 2);
            ldsm4t(bh[4], bh[5], bh[6], bh[7],
                   sbase + TL_BH + ((kk + lr) * 136 + ncol0 + 16 + lc) * 2);
            ldsm4t(bl[0], bl[1], bl[2], bl[3],
                   sbase + TL_BL + ((kk + lr) * 136 + ncol0 + lc) * 2);
            ldsm4t(bl[4], bl[5], bl[6], bl[7],
                   sbase + TL_BL + ((kk + lr) * 136 + ncol0 + 16 + lc) * 2);
#pragma unroll
            for (int mt = 0; mt < 2; mt++) {
                u32 ah[4], al[4];
                ldsm4(ah[0], ah[1], ah[2], ah[3],
                      sbase + TL_AH + ((mrow0 + mt * 16 + lr) * 72 + kk + lc) * 2);
                ldsm4(al[0], al[1], al[2], al[3],
                      sbase + TL_AL + ((mrow0 + mt * 16 + lr) * 72 + kk + lc) * 2);
#pragma unroll
                for (int nt = 0; nt < 4; nt++) {
                    mma16816(acc[mt][nt], ah, &bh[nt * 2]);
                    mma16816(acc[mt][nt], ah, &bl[nt * 2]);
                    mma16816(acc[mt][nt], al, &bh[nt * 2]);
                }
            }
        }
        __syncthreads();
    }

    // h1 epilogue
#pragma unroll
    for (int mt = 0; mt < 2; mt++) {
#pragma unroll
        for (int nt = 0; nt < 4; nt++) {
            int r = mrow0 + mt * 16 + g;
            int cl = ncol0 + nt * 8 + t * 2;
            float b0v = b1s[cl], b1v = b1s[cl + 1];
            u32 hh, ll;
            split2(fmaxf(acc[mt][nt][0] + b0v, 0.f),
                   fmaxf(acc[mt][nt][1] + b1v, 0.f), hh, ll);
            *reinterpret_cast<u32*>(smem + TL_H1H + r * 272 + cl * 2) = hh;
            *reinterpret_cast<u32*>(smem + TL_H1L + r * 272 + cl * 2) = ll;
            split2(fmaxf(acc[mt][nt][2] + b0v, 0.f),
                   fmaxf(acc[mt][nt][3] + b1v, 0.f), hh, ll);
            *reinterpret_cast<u32*>(smem + TL_H1H + (r + 8) * 272 + cl * 2) = hh;
            *reinterpret_cast<u32*>(smem + TL_H1L + (r + 8) * 272 + cl * 2) = ll;
        }
    }

    // ---- Phase 2: h2 = relu(h1 @ Wc2 + bc2), K = 128 ----
#pragma unroll
    for (int mt = 0; mt < 2; mt++)
#pragma unroll
        for (int nt = 0; nt < 4; nt++)
#pragma unroll
            for (int r = 0; r < 4; r++) acc[mt][nt][r] = 0.f;

    for (int c = 0; c < 2; c++) {
        const int k0 = c * 64;
        if (c == 1) {
            tail_cpB(sbase, TL_B2H, TL_B2L, g_Wc2h, g_Wc2l, k0);
            CP_COMMIT();
        }
        CP_WAIT0();
        __syncthreads();
#pragma unroll
        for (int k16 = 0; k16 < 4; k16++) {
            const int kk = k16 * 16;
            u32 bh[8], bl[8];
            ldsm4t(bh[0], bh[1], bh[2], bh[3],
                   sbase + TL_B2H + ((kk + lr) * 136 + ncol0 + lc) * 2);
            ldsm4t(bh[4], bh[5], bh[6], bh[7],
                   sbase + TL_B2H + ((kk + lr) * 136 + ncol0 + 16 + lc) * 2);
            ldsm4t(bl[0], bl[1], bl[2], bl[3],
                   sbase + TL_B2L + ((kk + lr) * 136 + ncol0 + lc) * 2);
            ldsm4t(bl[4], bl[5], bl[6], bl[7],
                   sbase + TL_B2L + ((kk + lr) * 136 + ncol0 + 16 + lc) * 2);
#pragma unroll
            for (int mt = 0; mt < 2; mt++) {
                u32 ah[4], al[4];
                ldsm4(ah[0], ah[1], ah[2], ah[3],
                      sbase + TL_H1H + ((mrow0 + mt * 16 + lr) * 136 + k0 + kk + lc) * 2);
                ldsm4(al[0], al[1], al[2], al[3],
                      sbase + TL_H1L + ((mrow0 + mt * 16 + lr) * 136 + k0 + kk + lc) * 2);
#pragma unroll
                for (int nt = 0; nt < 4; nt++) {
                    mma16816(acc[mt][nt], ah, &bh[nt * 2]);
                    mma16816(acc[mt][nt], ah, &bl[nt * 2]);
                    mma16816(acc[mt][nt], al, &bh[nt * 2]);
                }
            }
        }
        __syncthreads();
    }

    // ---- head ----
    {
        float ph[4][2];
#pragma unroll
        for (int i = 0; i < 4; i++) { ph[i][0] = 0.f; ph[i][1] = 0.f; }
#pragma unroll
        for (int mt = 0; mt < 2; mt++) {
#pragma unroll
            for (int nt = 0; nt < 4; nt++) {
                int cl = ncol0 + nt * 8 + t * 2;
                float b0v = b2s[cl], b1v = b2s[cl + 1];
                float w00 = W3s[cl * 2], w01 = W3s[cl * 2 + 1];
                float w10 = W3s[(cl + 1) * 2], w11 = W3s[(cl + 1) * 2 + 1];
                float h0 = fmaxf(acc[mt][nt][0] + b0v, 0.f);
                float h1 = fmaxf(acc[mt][nt][1] + b1v, 0.f);
                ph[mt * 2][0] = fmaf(h0, w00, fmaf(h1, w10, ph[mt * 2][0]));
                ph[mt * 2][1] = fmaf(h0, w01, fmaf(h1, w11, ph[mt * 2][1]));
                h0 = fmaxf(acc[mt][nt][2] + b0v, 0.f);
                h1 = fmaxf(acc[mt][nt][3] + b1v, 0.f);
                ph[mt * 2 + 1][0] = fmaf(h0, w00, fmaf(h1, w10, ph[mt * 2 + 1][0]));
                ph[mt * 2 + 1][1] = fmaf(h0, w01, fmaf(h1, w11, ph[mt * 2 + 1][1]));
            }
        }
#pragma unroll
        for (int i = 0; i < 4; i++) {
#pragma unroll
            for (int a = 0; a < 2; a++) {
                ph[i][a] += __shfl_xor_sync(0xffffffffu, ph[i][a], 1);
                ph[i][a] += __shfl_xor_sync(0xffffffffu, ph[i][a], 2);
            }
        }
        if (t == 0) {
#pragma unroll
            for (int i = 0; i < 4; i++) {
                int row = mrow0 + (i >> 1) * 16 + (i & 1) * 8 + g;
                pt[row * 8 + nwarp * 2 + 0] = ph[i][0];
                pt[row * 8 + nwarp * 2 + 1] = ph[i][1];
            }
        }
    }
    __syncthreads();
    if (tid < 128) {
        int row = tid >> 1, a = tid & 1;
        float s = pt[row * 8 + a] + pt[row * 8 + 2 + a] +
                  pt[row * 8 + 4 + a] + pt[row * 8 + 6 + a];
        out[(size_t)(row0 + row) * 2 + a] = tanhf(s + b3s[a]);
    }
}

// ---------------------------------------------------------------------------
// kernel_launch
// ---------------------------------------------------------------------------
extern "C" void kernel_launch(void* const* d_in, const int* in_sizes, int n_in,
                              void* d_out, int out_size) {
    const float* S0  = (const float*)d_in[0];
    const float* S1  = (const float*)d_in[1];
    const float* S2  = (const float*)d_in[2];
    const float* W0  = (const float*)d_in[3];
    const float* b0  = (const float*)d_in[4];
    const float* Wg  = (const float*)d_in[5];
    const float* bg  = (const float*)d_in[6];
    const float* Ws1 = (const float*)d_in[7];
    const float* bs1 = (const float*)d_in[8];
    const float* Ws2 = (const float*)d_in[9];
    const float* bs2 = (const float*)d_in[10];
    const float* Wq  = (const float*)d_in[11];
    const float* Wk  = (const float*)d_in[12];
    const float* Wv  = (const float*)d_in[13];
    const float* Wc1 = (const float*)d_in[14];
    const float* bc1 = (const float*)d_in[15];
    const float* Wc2 = (const float*)d_in[16];
    const float* bc2 = (const float*)d_in[17];
    const float* Wc3 = (const float*)d_in[18];
    const float* bc3 = (const float*)d_in[19];
    float* out = (float*)d_out;

    void* p;
    cudaGetSymbolAddress(&p, g_concat); float* C = (float*)p;

    cudaFuncSetAttribute(k_attn5, cudaFuncAttributeMaxDynamicSharedMemorySize,
                         ATTN_SMEM_BYTES);
    cudaFuncSetAttribute(k1_gemm, cudaFuncAttributeMaxDynamicSharedMemorySize,
                         K1_SMEM_BYTES);
    cudaFuncSetAttribute(k_tail, cudaFuncAttributeMaxDynamicSharedMemorySize,
                         TAIL_SMEM_BYTES);

    // K0: split all weights (+ M = Wq@Wk^T), 2 elems/thread
    k_split<<<232, 256>>>(Wg, Wc1, Wc2, Ws2, Wv, Wq, Wk);
    // K1: env_e -> g_concat[:,64:128]  (64-row tiles, 3 CTA/SM)
    k1_gemm<<<B_TOT / 64, 256, K1_SMEM_BYTES>>>(S1, bg, C);
    // K2: own_e + attention -> g_concat[:,0:64], [:,128:192]
    k_attn5<<<B_TOT / 16, 256, ATTN_SMEM_BYTES>>>(S0, S2, W0, b0, Ws1, bs1, bs2);
    // K3: fused tail -> out
    k_tail<<<B_TOT / 64, 256, TAIL_SMEM_BYTES>>>(bc1, bc2, Wc3, bc3, out);
}

// round 17
// speedup vs baseline: 1.0310x; 1.0310x over previous
#include <cuda_runtime.h>
#include <cuda_bf16.h>
#include <math.h>
#include <stdint.h>

#define B_TOT 65536
// H=64, HC=128, N=8, OBS0=6, OBS1=1024, OBS2=7, NA=2

typedef unsigned long long u64;
typedef unsigned short u16;
typedef unsigned int u32;

// ---------------------------------------------------------------------------
// helpers
// ---------------------------------------------------------------------------
static __device__ __forceinline__ uint32_t smem_u32(const void* p) {
    uint32_t a;
    asm("{ .reg .u64 t; cvta.to.shared.u64 t, %1; cvt.u32.u64 %0, t; }"
        : "=r"(a) : "l"(p));
    return a;
}
static __device__ __forceinline__ void mma16816(float* c, const u32* a, const u32* b) {
    asm volatile(
        "mma.sync.aligned.m16n8k16.row.col.f32.bf16.bf16.f32 "
        "{%0,%1,%2,%3}, {%4,%5,%6,%7}, {%8,%9}, {%0,%1,%2,%3};"
        : "+f"(c[0]), "+f"(c[1]), "+f"(c[2]), "+f"(c[3])
        : "r"(a[0]), "r"(a[1]), "r"(a[2]), "r"(a[3]), "r"(b[0]), "r"(b[1]));
}
static __device__ __forceinline__ void ldsm4(u32& r0, u32& r1, u32& r2, u32& r3, u32 a) {
    asm volatile("ldmatrix.sync.aligned.m8n8.x4.shared.b16 {%0,%1,%2,%3}, [%4];"
                 : "=r"(r0), "=r"(r1), "=r"(r2), "=r"(r3) : "r"(a));
}
static __device__ __forceinline__ void ldsm4t(u32& r0, u32& r1, u32& r2, u32& r3, u32 a) {
    asm volatile("ldmatrix.sync.aligned.m8n8.x4.trans.shared.b16 {%0,%1,%2,%3}, [%4];"
                 : "=r"(r0), "=r"(r1), "=r"(r2), "=r"(r3) : "r"(a));
}
// exact pair split: h2 = {x0>>16, x1>>16}; l2 = bf16rn(residuals)
static __device__ __forceinline__ void split2(float x0, float x1, u32& h2, u32& l2) {
    u32 b0 = __float_as_uint(x0), b1 = __float_as_uint(x1);
    asm("prmt.b32 %0, %1, %2, 0x7632;" : "=r"(h2) : "r"(b0), "r"(b1));
    float r0 = x0 - __uint_as_float(b0 & 0xffff0000u);
    float r1 = x1 - __uint_as_float(b1 & 0xffff0000u);
    asm("cvt.rn.bf16x2.f32 %0, %1, %2;" : "=r"(l2) : "f"(r1), "f"(r0));
}
#define CP_A16(d, s) \
    asm volatile("cp.async.ca.shared.global [%0], [%1], 16;" :: "r"(d), "l"(s) : "memory")
#define CP_COMMIT() asm volatile("cp.async.commit_group;" ::: "memory")
#define CP_WAIT0()  asm volatile("cp.async.wait_group 0;" ::: "memory")

// ---------------------------------------------------------------------------
// Scratch (static device globals: allocation-free)
// ---------------------------------------------------------------------------
__device__ float g_concat[(size_t)B_TOT * 192];
// pre-split weights, [k][n] row-major bf16
__device__ u16 g_Wgh[1024 * 64],  g_Wgl[1024 * 64];
__device__ u16 g_Wc1h[192 * 128], g_Wc1l[192 * 128];
__device__ u16 g_Wc2h[128 * 128], g_Wc2l[128 * 128];
__device__ u16 g_Ws2h[64 * 64],   g_Ws2l[64 * 64];
__device__ u16 g_Mh[64 * 64],     g_Ml[64 * 64];      // Wq@Wk^T split
__device__ u16 g_Wvh[64 * 64],    g_Wvl[64 * 64];

// ---------------------------------------------------------------------------
// K0: split all weights into bf16 hi/lo; also computes M = Wq@Wk^T (split)
// ---------------------------------------------------------------------------
__global__ void k_split(const float* __restrict__ Wg, const float* __restrict__ Wc1,
                        const float* __restrict__ Wc2, const float* __restrict__ Ws2,
                        const float* __restrict__ Wv,
                        const float* __restrict__ Wq, const float* __restrict__ Wk) {
    int i = blockIdx.x * 256 + threadIdx.x;
    float x;
    u16 *dh, *dl; int off;
    if (i < 65536)       { x = Wg[i];           dh = g_Wgh;  dl = g_Wgl;  off = i; }
    else if (i < 90112)  { off = i - 65536;  x = Wc1[off]; dh = g_Wc1h; dl = g_Wc1l; }
    else if (i < 106496) { off = i - 90112;  x = Wc2[off]; dh = g_Wc2h; dl = g_Wc2l; }
    else if (i < 110592) { off = i - 106496; x = Ws2[off]; dh = g_Ws2h; dl = g_Ws2l; }
    else if (i < 114688) { off = i - 110592; x = Wv[off];  dh = g_Wvh;  dl = g_Wvl; }
    else if (i < 118784) {
        off = i - 114688;
        int r = off >> 6, j = off & 63;
        float s = 0.f;
#pragma unroll
        for (int h = 0; h < 64; h++) s = fmaf(Wq[r * 64 + h], Wk[j * 64 + h], s);
        x = s; dh = g_Mh; dl = g_Ml;
    } else return;
    __nv_bfloat16 hb = __float2bfloat16(x);
    __nv_bfloat16 lb = __float2bfloat16(x - __bfloat162float(hb));
    dh[off] = __bfloat16_as_ushort(hb);
    dl[off] = __bfloat16_as_ushort(lb);
}

// ---------------------------------------------------------------------------
// K1 v3 (champion): env_e = relu(S1 @ Wg + bg) -> g_concat[:,64:128]
// 64-row tiles, grid 1024, 3 CTAs/SM. B via cp.async. Warp tile 32x16 (2m x 4n).
// smem: Ah@0 Al@9216 Bh@18432 Bl@27648 bias@36864  (37.1 KB)
// ---------------------------------------------------------------------------
#define K1_SMEM_BYTES (36864 + 256)

__global__ __launch_bounds__(256, 3)
void k1_gemm(const float* __restrict__ A, const float* __restrict__ bias,
             float* __restrict__ C) {
    extern __shared__ char smem[];
    const u32 sbase = smem_u32(smem);
    const u32 ah_b = sbase, al_b = sbase + 9216;
    const u32 bh_b = sbase + 18432, bl_b = sbase + 27648;
    float* bs = (float*)(smem + 36864);

    const int tid = threadIdx.x;
    const int wid = tid >> 5, lane = tid & 31;
    const int row0 = blockIdx.x * 64;
    const int mwarp = wid >> 2, nwarp = wid & 3;
    const int g = lane >> 2, t = lane & 3;
    const int lr = lane & 15, lc = (lane >> 4) << 3;
    const int mrow0 = mwarp * 32, ncol0 = nwarp * 16;

    if (tid < 64) bs[tid] = bias[tid];

    float acc[2][2][4];
#pragma unroll
    for (int mt = 0; mt < 2; mt++)
#pragma unroll
        for (int nt = 0; nt < 2; nt++)
#pragma unroll
            for (int r = 0; r < 4; r++) acc[mt][nt][r] = 0.f;

    for (int c = 0; c < 16; c++) {
        const int k0 = c * 64;
        {   // B tiles via cp.async (overlapped by A convert)
            const int kk = tid >> 2, cg = (tid & 3) * 16;
            const u16* sh = g_Wgh + (size_t)(k0 + kk) * 64 + cg;
            const u16* sl = g_Wgl + (size_t)(k0 + kk) * 64 + cg;
            u32 dh = bh_b + kk * 144 + cg * 2;
            u32 dl = bl_b + kk * 144 + cg * 2;
            CP_A16(dh, sh);      CP_A16(dh + 16, sh + 8);
            CP_A16(dl, sl);      CP_A16(dl + 16, sl + 8);
            CP_COMMIT();
        }
        {   // A chunk [64 x 64] fp32 -> split bf16 (4 float4/thread)
            const int m = tid >> 2, cq = tid & 3;
            const float* src = A + (size_t)(row0 + m) * 1024 + k0 + cq * 16;
            char* dh = smem + m * 144 + cq * 32;
            char* dl = smem + 9216 + m * 144 + cq * 32;
#pragma unroll
            for (int q = 0; q < 4; q++) {
                float4 v = *reinterpret_cast<const float4*>(src + q * 4);
                uint2 hh, ll;
                split2(v.x, v.y, hh.x, ll.x);
                split2(v.z, v.w, hh.y, ll.y);
                *reinterpret_cast<uint2*>(dh + q * 8) = hh;
                *reinterpret_cast<uint2*>(dl + q * 8) = ll;
            }
        }
        CP_WAIT0();
        __syncthreads();

#pragma unroll
        for (int k16 = 0; k16 < 4; k16++) {
            const int kk = k16 * 16;
            u32 bh[4], bl[4];
            ldsm4t(bh[0], bh[1], bh[2], bh[3], bh_b + ((kk + lr) * 72 + ncol0 + lc) * 2);
            ldsm4t(bl[0], bl[1], bl[2], bl[3], bl_b + ((kk + lr) * 72 + ncol0 + lc) * 2);
#pragma unroll
            for (int mt = 0; mt < 2; mt++) {
                u32 ah[4], al[4];
                ldsm4(ah[0], ah[1], ah[2], ah[3],
                      ah_b + ((mrow0 + mt * 16 + lr) * 72 + kk + lc) * 2);
                ldsm4(al[0], al[1], al[2], al[3],
                      al_b + ((mrow0 + mt * 16 + lr) * 72 + kk + lc) * 2);
#pragma unroll
                for (int nt = 0; nt < 2; nt++) {
                    mma16816(acc[mt][nt], ah, &bh[nt * 2]);
                    mma16816(acc[mt][nt], ah, &bl[nt * 2]);
                    mma16816(acc[mt][nt], al, &bh[nt * 2]);
                }
            }
        }
        __syncthreads();
    }

#pragma unroll
    for (int mt = 0; mt < 2; mt++) {
#pragma unroll
        for (int nt = 0; nt < 2; nt++) {
            int r = row0 + mrow0 + mt * 16 + g;
            int cl = ncol0 + nt * 8 + t * 2;
            float b0v = bs[cl], b1v = bs[cl + 1];
            float2 v0, v1;
            v0.x = fmaxf(acc[mt][nt][0] + b0v, 0.f);
            v0.y = fmaxf(acc[mt][nt][1] + b1v, 0.f);
            v1.x = fmaxf(acc[mt][nt][2] + b0v, 0.f);
            v1.y = fmaxf(acc[mt][nt][3] + b1v, 0.f);
            *reinterpret_cast<float2*>(C + (size_t)r * 192 + 64 + cl) = v0;
            *reinterpret_cast<float2*>(C + (size_t)(r + 8) * 192 + 64 + cl) = v1;
        }
    }
}

// ---------------------------------------------------------------------------
// K2 v5: fused attention (champion, unchanged)
// ---------------------------------------------------------------------------
#define AT_E1H   0
#define AT_E1L   18432
#define AT_E2    0
#define AT_WS2H  36864
#define AT_WS2L  46080
#define AT_MH    55296
#define AT_ML    64512
#define AT_WVH   73728
#define AT_WVL   82944
#define AT_OWNH  92160
#define AT_OWNL  94464
#define AT_TT    96768
#define AT_W0    101120
#define AT_WS1   102656
#define AT_B0    104448
#define AT_BS1   104704
#define AT_BS2   104960
#define AT_SC    105216
#define AT_AL    105728
#define AT_MK    106240
#define ATTN_SMEM_BYTES 106752

__global__ __launch_bounds__(256, 2)
void k_attn5(const float* __restrict__ S0, const float* __restrict__ S2,
             const float* __restrict__ W0, const float* __restrict__ b0,
             const float* __restrict__ Ws1, const float* __restrict__ bs1,
             const float* __restrict__ bs2) {
    extern __shared__ char smem[];
    float* E2   = (float*)(smem + AT_E2);
    float* tt   = (float*)(smem + AT_TT);
    float* W0s  = (float*)(smem + AT_W0);
    float* Ws1s = (float*)(smem + AT_WS1);
    float* b0s  = (float*)(smem + AT_B0);
    float* bs1s = (float*)(smem + AT_BS1);
    float* bs2s = (float*)(smem + AT_BS2);
    float* sc   = (float*)(smem + AT_SC);
    float* al   = (float*)(smem + AT_AL);
    float* mk   = (float*)(smem + AT_MK);
    const u32 sbase = smem_u32(smem);
    const u32 e1h_b = sbase + AT_E1H, e1l_b = sbase + AT_E1L;
    const u32 wsh_b = sbase + AT_WS2H, wsl_b = sbase + AT_WS2L;
    const u32 mh_b  = sbase + AT_MH,   ml_b  = sbase + AT_ML;
    const u32 wvh_b = sbase + AT_WVH,  wvl_b = sbase + AT_WVL;
    const u32 ownh_b = sbase + AT_OWNH, ownl_b = sbase + AT_OWNL;

    const int tid = threadIdx.x;
    const int wid = tid >> 5, lane = tid & 31;
    const int gb0 = blockIdx.x * 16;

    if (tid < 96)  reinterpret_cast<float4*>(W0s)[tid]  =
        reinterpret_cast<const float4*>(W0)[tid];
    if (tid >= 96 && tid < 208) reinterpret_cast<float4*>(Ws1s)[tid - 96] =
        reinterpret_cast<const float4*>(Ws1)[tid - 96];
    if (tid >= 208 && tid < 224) reinterpret_cast<float4*>(b0s)[tid - 208] =
        reinterpret_cast<const float4*>(b0)[tid - 208];
    if (tid >= 224 && tid < 240) reinterpret_cast<float4*>(bs1s)[tid - 224] =
        reinterpret_cast<const float4*>(bs1)[tid - 224];
    if (tid >= 240) reinterpret_cast<float4*>(bs2s)[tid - 240] =
        reinterpret_cast<const float4*>(bs2)[tid - 240];
    {
        const int kk = tid >> 2, cg = (tid & 3) * 16;
        const int go = kk * 64 + cg;
        const int so = kk * 144 + cg * 2;
        const u16* srcs[6] = {g_Ws2h, g_Ws2l, g_Mh, g_Ml, g_Wvh, g_Wvl};
        const int offs[6] = {AT_WS2H, AT_WS2L, AT_MH, AT_ML, AT_WVH, AT_WVL};
#pragma unroll
        for (int a = 0; a < 6; a++) {
            char* d = smem + offs[a] + so;
            *reinterpret_cast<uint4*>(d)      = *reinterpret_cast<const uint4*>(srcs[a] + go);
            *reinterpret_cast<uint4*>(d + 16) = *reinterpret_cast<const uint4*>(srcs[a] + go + 8);
        }
    }

    // P1: own_e
    {
        const int row = tid >> 4, c0 = (tid & 15) * 4;
        const float* s0 = S0 + (size_t)(gb0 + row) * 6;
        float x0 = s0[0], x1 = s0[1], x2 = s0[2], x3 = s0[3], x4 = s0[4], x5 = s0[5];
        float* og = g_concat + (size_t)(gb0 + row) * 192;
        __syncthreads();
        float4 a4 = *reinterpret_cast<const float4*>(b0s + c0);
#pragma unroll
        for (int kk = 0; kk < 6; kk++) {
            float xv = (kk == 0) ? x0 : (kk == 1) ? x1 : (kk == 2) ? x2 :
                       (kk == 3) ? x3 : (kk == 4) ? x4 : x5;
            float4 w4 = *reinterpret_cast<const float4*>(W0s + kk * 64 + c0);
            a4.x = fmaf(xv, w4.x, a4.x); a4.y = fmaf(xv, w4.y, a4.y);
            a4.z = fmaf(xv, w4.z, a4.z); a4.w = fmaf(xv, w4.w, a4.w);
        }
        a4.x = fmaxf(a4.x, 0.f); a4.y = fmaxf(a4.y, 0.f);
        a4.z = fmaxf(a4.z, 0.f); a4.w = fmaxf(a4.w, 0.f);
        uint2 hh, ll;
        split2(a4.x, a4.y, hh.x, ll.x);
        split2(a4.z, a4.w, hh.y, ll.y);
        *reinterpret_cast<uint2*>(smem + AT_OWNH + row * 144 + c0 * 2) = hh;
        *reinterpret_cast<uint2*>(smem + AT_OWNL + row * 144 + c0 * 2) = ll;
        *reinterpret_cast<float4*>(og + c0) = a4;
    }

    // P2: E1
    {
        const int rr = tid >> 1, h = tid & 1, j0 = h * 32;
        const float* s2 = S2 + ((size_t)gb0 * 8 + rr) * 7;
        float y0 = s2[0], y1 = s2[1], y2 = s2[2], y3 = s2[3], y4 = s2[4], y5 = s2[5], y6 = s2[6];
        if (h == 0)
            mk[rr] = ((y0 + y1 + y2 + y3 + y4 + y5 + y6) != 0.f) ? 1.f : 0.f;
        float a[32];
#pragma unroll
        for (int q = 0; q < 8; q++) {
            float4 v4 = *reinterpret_cast<const float4*>(bs1s + j0 + q * 4);
            a[q * 4 + 0] = v4.x; a[q * 4 + 1] = v4.y;
            a[q * 4 + 2] = v4.z; a[q * 4 + 3] = v4.w;
        }
#pragma unroll
        for (int kk = 0; kk < 7; kk++) {
            float yv = (kk == 0) ? y0 : (kk == 1) ? y1 : (kk == 2) ? y2 :
                       (kk == 3) ? y3 : (kk == 4) ? y4 : (kk == 5) ? y5 : y6;
#pragma unroll
            for (int q = 0; q < 8; q++) {
                float4 w4 = *reinterpret_cast<const float4*>(Ws1s + kk * 64 + j0 + q * 4);
                a[q * 4 + 0] = fmaf(yv, w4.x, a[q * 4 + 0]);
                a[q * 4 + 1] = fmaf(yv, w4.y, a[q * 4 + 1]);
                a[q * 4 + 2] = fmaf(yv, w4.z, a[q * 4 + 2]);
                a[q * 4 + 3] = fmaf(yv, w4.w, a[q * 4 + 3]);
            }
        }
#pragma unroll
        for (int j = 0; j < 32; j++) a[j] = fmaxf(a[j], 0.f);
        char* dh = smem + AT_E1H + rr * 144 + j0 * 2;
        char* dl = smem + AT_E1L + rr * 144 + j0 * 2;
#pragma unroll
        for (int q = 0; q < 32; q += 8) {
            uint4 vh, vl;
            split2(a[q + 0], a[q + 1], vh.x, vl.x);
            split2(a[q + 2], a[q + 3], vh.y, vl.y);
            split2(a[q + 4], a[q + 5], vh.z, vl.z);
            split2(a[q + 6], a[q + 7], vh.w, vl.w);
            *reinterpret_cast<uint4*>(dh + q * 2) = vh;
            *reinterpret_cast<uint4*>(dl + q * 2) = vl;
        }
    }
    __syncthreads();

    // P3: E2 = relu(E1 @ Ws2 + bs2) via HMMA
    float acc[2][4][4];
    {
        const int mwarp = wid >> 1, nwarp = wid & 1;
        const int lr = lane & 15, lc = (lane >> 4) << 3;
        const int mrow0 = mwarp * 32, ncol0 = nwarp * 32;
#pragma unroll
        for (int mt = 0; mt < 2; mt++)
#pragma unroll
            for (int nt = 0; nt < 4; nt++)
#pragma unroll
                for (int r = 0; r < 4; r++) acc[mt][nt][r] = 0.f;

#pragma unroll
        for (int k16 = 0; k16 < 4; k16++) {
            const int kk = k16 * 16;
            u32 bh[8], bl[8];
            ldsm4t(bh[0], bh[1], bh[2], bh[3], wsh_b + ((kk + lr) * 72 + ncol0 + lc) * 2);
            ldsm4t(bh[4], bh[5], bh[6], bh[7], wsh_b + ((kk + lr) * 72 + ncol0 + 16 + lc) * 2);
            ldsm4t(bl[0], bl[1], bl[2], bl[3], wsl_b + ((kk + lr) * 72 + ncol0 + lc) * 2);
            ldsm4t(bl[4], bl[5], bl[6], bl[7], wsl_b + ((kk + lr) * 72 + ncol0 + 16 + lc) * 2);
#pragma unroll
            for (int mt = 0; mt < 2; mt++) {
                u32 ah[4], alr[4];
                ldsm4(ah[0], ah[1], ah[2], ah[3],
                      e1h_b + ((mrow0 + mt * 16 + lr) * 72 + kk + lc) * 2);
                ldsm4(alr[0], alr[1], alr[2], alr[3],
                      e1l_b + ((mrow0 + mt * 16 + lr) * 72 + kk + lc) * 2);
#pragma unroll
                for (int nt = 0; nt < 4; nt++) {
                    mma16816(acc[mt][nt], ah, &bh[nt * 2]);
                    mma16816(acc[mt][nt], ah, &bl[nt * 2]);
                    mma16816(acc[mt][nt], alr, &bh[nt * 2]);
                }
            }
        }
    }
    __syncthreads();

    // E2 epilogue + P4 (own@M HMMA)
    {
        const int mwarp = wid >> 1, nwarp = wid & 1;
        const int g = lane >> 2, t = lane & 3;
        const int mrow0 = mwarp * 32, ncol0 = nwarp * 32;
#pragma unroll
        for (int mt = 0; mt < 2; mt++) {
#pragma unroll
            for (int nt = 0; nt < 4; nt++) {
                int r = mrow0 + mt * 16 + g;
                int cl = ncol0 + nt * 8 + t * 2;
                float b0v = bs2s[cl], b1v = bs2s[cl + 1];
                float2 v0, v1;
                v0.x = fmaxf(acc[mt][nt][0] + b0v, 0.f);
                v0.y = fmaxf(acc[mt][nt][1] + b1v, 0.f);
                v1.x = fmaxf(acc[mt][nt][2] + b0v, 0.f);
                v1.y = fmaxf(acc[mt][nt][3] + b1v, 0.f);
                *reinterpret_cast<float2*>(E2 + r * 68 + cl) = v0;
                *reinterpret_cast<float2*>(E2 + (r + 8) * 68 + cl) = v1;
            }
        }
    }
    if (wid < 4) {
        const int ncol0 = wid * 16;
        const int lr = lane & 15, lc = (lane >> 4) << 3;
        float tac[2][4];
#pragma unroll
        for (int nt = 0; nt < 2; nt++)
#pragma unroll
            for (int r = 0; r < 4; r++) tac[nt][r] = 0.f;
#pragma unroll
        for (int k16 = 0; k16 < 4; k16++) {
            const int kk = k16 * 16;
            u32 bh[4], bl[4], ah[4], alr[4];
            ldsm4t(bh[0], bh[1], bh[2], bh[3], mh_b + ((kk + lr) * 72 + ncol0 + lc) * 2);
            ldsm4t(bl[0], bl[1], bl[2], bl[3], ml_b + ((kk + lr) * 72 + ncol0 + lc) * 2);
            ldsm4(ah[0], ah[1], ah[2], ah[3], ownh_b + lr * 144 + (kk + lc) * 2);
            ldsm4(alr[0], alr[1], alr[2], alr[3], ownl_b + lr * 144 + (kk + lc) * 2);
#pragma unroll
            for (int nt = 0; nt < 2; nt++) {
                mma16816(tac[nt], ah, &bh[nt * 2]);
                mma16816(tac[nt], ah, &bl[nt * 2]);
                mma16816(tac[nt], alr, &bh[nt * 2]);
            }
        }
        const int g = lane >> 2, tq = lane & 3;
#pragma unroll
        for (int nt = 0; nt < 2; nt++) {
            int cl = ncol0 + nt * 8 + tq * 2;
            *reinterpret_cast<float2*>(tt + g * 68 + cl) =
                make_float2(tac[nt][0], tac[nt][1]);
            *reinterpret_cast<float2*>(tt + (g + 8) * 68 + cl) =
                make_float2(tac[nt][2], tac[nt][3]);
        }
    }
    __syncthreads();

    // P5: scores
    {
        const int rr = tid >> 1, h = tid & 1, k0 = h * 32;
        const int lb = rr >> 3;
        float s = 0.f;
#pragma unroll
        for (int k = 0; k < 32; k += 4) {
            float4 t4 = *reinterpret_cast<const float4*>(tt + lb * 68 + k0 + k);
            float4 e4 = *reinterpret_cast<const float4*>(E2 + rr * 68 + k0 + k);
            s = fmaf(t4.x, e4.x, s); s = fmaf(t4.y, e4.y, s);
            s = fmaf(t4.z, e4.z, s); s = fmaf(t4.w, e4.w, s);
        }
        s += __shfl_xor_sync(0xffffffffu, s, 1);
        if (h == 0)
            sc[rr] = (mk[rr] != 0.f) ? (s * 0.125f) : __int_as_float(0xff800000);
    }
    __syncthreads();

    // P6: softmax
    if (tid < 16) {
        float m = __int_as_float(0xff800000);
#pragma unroll
        for (int n = 0; n < 8; n++) m = fmaxf(m, sc[tid * 8 + n]);
        float e[8]; float ssum = 0.f;
#pragma unroll
        for (int n = 0; n < 8; n++) { float v = expf(sc[tid * 8 + n] - m); e[n] = v; ssum += v; }
        float inv = 1.f / ssum;
#pragma unroll
        for (int n = 0; n < 8; n++) al[tid * 8 + n] = e[n] * inv;
    }
    __syncthreads();

    // P7a: wsum -> split bf16 (aliases own buffers)
    {
        const int row = tid >> 4, c0 = (tid & 15) * 4;
        float4 a4 = {0.f, 0.f, 0.f, 0.f};
#pragma unroll
        for (int n = 0; n < 8; n++) {
            float av = al[row * 8 + n];
            float4 e4 = *reinterpret_cast<const float4*>(E2 + (row * 8 + n) * 68 + c0);
            a4.x = fmaf(av, e4.x, a4.x); a4.y = fmaf(av, e4.y, a4.y);
            a4.z = fmaf(av, e4.z, a4.z); a4.w = fmaf(av, e4.w, a4.w);
        }
        uint2 hh, ll;
        split2(a4.x, a4.y, hh.x, ll.x);
        split2(a4.z, a4.w, hh.y, ll.y);
        *reinterpret_cast<uint2*>(smem + AT_OWNH + row * 144 + c0 * 2) = hh;
        *reinterpret_cast<uint2*>(smem + AT_OWNL + row * 144 + c0 * 2) = ll;
    }
    __syncthreads();

    // P7b: v_att = wsum @ Wv via HMMA
    if (wid < 4) {
        const int ncol0 = wid * 16;
        const int lr = lane & 15, lc = (lane >> 4) << 3;
        float vac[2][4];
#pragma unroll
        for (int nt = 0; nt < 2; nt++)
#pragma unroll
            for (int r = 0; r < 4; r++) vac[nt][r] = 0.f;
#pragma unroll
        for (int k16 = 0; k16 < 4; k16++) {
            const int kk = k16 * 16;
            u32 bh[4], bl[4], ah[4], alr[4];
            ldsm4t(bh[0], bh[1], bh[2], bh[3], wvh_b + ((kk + lr) * 72 + ncol0 + lc) * 2);
            ldsm4t(bl[0], bl[1], bl[2], bl[3], wvl_b + ((kk + lr) * 72 + ncol0 + lc) * 2);
            ldsm4(ah[0], ah[1], ah[2], ah[3], ownh_b + lr * 144 + (kk + lc) * 2);
            ldsm4(alr[0], alr[1], alr[2], alr[3], ownl_b + lr * 144 + (kk + lc) * 2);
#pragma unroll
            for (int nt = 0; nt < 2; nt++) {
                mma16816(vac[nt], ah, &bh[nt * 2]);
                mma16816(vac[nt], ah, &bl[nt * 2]);
                mma16816(vac[nt], alr, &bh[nt * 2]);
            }
        }
        const int g = lane >> 2, tq = lane & 3;
#pragma unroll
        for (int nt = 0; nt < 2; nt++) {
            int cl = ncol0 + nt * 8 + tq * 2;
            *reinterpret_cast<float2*>(g_concat + (size_t)(gb0 + g) * 192 + 128 + cl) =
                make_float2(vac[nt][0], vac[nt][1]);
            *reinterpret_cast<float2*>(g_concat + (size_t)(gb0 + g + 8) * 192 + 128 + cl) =
                make_float2(vac[nt][2], vac[nt][3]);
        }
    }
}

// ---------------------------------------------------------------------------
// K3: fused tail (champion, unchanged)
// ---------------------------------------------------------------------------
#define TL_AH   0
#define TL_AL   9216
#define TL_BH   18432
#define TL_BL   35840
#define TL_H1H  0
#define TL_H1L  17408
#define TL_B2H  53248
#define TL_B2L  70656
#define TL_W3   88064
#define TL_BC1  89088
#define TL_BC2  89600
#define TL_PT   90112
#define TAIL_SMEM_BYTES 92160

static __device__ __forceinline__ void tail_cpB(u32 sbase, int offH, int offL,
                                                const u16* gh, const u16* gl, int k0) {
    const int tid = threadIdx.x;
    const int kk = tid >> 2, cq = tid & 3;
    const u16* sh = gh + (size_t)(k0 + kk) * 128 + cq * 32;
    const u16* sl = gl + (size_t)(k0 + kk) * 128 + cq * 32;
    u32 dh = sbase + offH + kk * 272 + cq * 64;
    u32 dl = sbase + offL + kk * 272 + cq * 64;
#pragma unroll
    for (int q = 0; q < 4; q++) {
        CP_A16(dh + q * 16, sh + q * 8);
        CP_A16(dl + q * 16, sl + q * 8);
    }
}

__global__ __launch_bounds__(256, 2)
void k_tail(const float* __restrict__ bc1, const float* __restrict__ bc2,
            const float* __restrict__ Wc3, const float* __restrict__ bc3,
            float* __restrict__ out) {
    extern __shared__ char smem[];
    const u32 sbase = smem_u32(smem);
    float* W3s = (float*)(smem + TL_W3);
    float* b1s = (float*)(smem + TL_BC1);
    float* b2s = (float*)(smem + TL_BC2);
    float* pt  = (float*)(smem + TL_PT);
    __shared__ float b3s[2];

    const int tid = threadIdx.x;
    const int wid = tid >> 5, lane = tid & 31;
    const int row0 = blockIdx.x * 64;
    const int mwarp = wid >> 2, nwarp = wid & 3;
    const int g = lane >> 2, t = lane & 3;
    const int lr = lane & 15, lc = (lane >> 4) << 3;
    const int mrow0 = mwarp * 32, ncol0 = nwarp * 32;

    if (tid < 128) b1s[tid] = bc1[tid];
    else b2s[tid - 128] = bc2[tid - 128];
    if (tid < 64) reinterpret_cast<float4*>(W3s)[tid] =
        reinterpret_cast<const float4*>(Wc3)[tid];
    if (tid == 0) { b3s[0] = bc3[0]; b3s[1] = bc3[1]; }

    tail_cpB(sbase, TL_B2H, TL_B2L, g_Wc2h, g_Wc2l, 0);
    CP_COMMIT();

    float acc[2][4][4];
#pragma unroll
    for (int mt = 0; mt < 2; mt++)
#pragma unroll
        for (int nt = 0; nt < 4; nt++)
#pragma unroll
            for (int r = 0; r < 4; r++) acc[mt][nt][r] = 0.f;

    // ---- Phase 1: h1 = relu(concat @ Wc1 + bc1), K = 192 ----
    for (int c = 0; c < 3; c++) {
        const int k0 = c * 64;
        tail_cpB(sbase, TL_BH, TL_BL, g_Wc1h, g_Wc1l, k0);
        CP_COMMIT();
        {
            const int m = tid >> 2, cq = tid & 3;
            const float* src = g_concat + (size_t)(row0 + m) * 192 + k0 + cq * 16;
            char* dh = smem + TL_AH + m * 144 + cq * 32;
            char* dl = smem + TL_AL + m * 144 + cq * 32;
#pragma unroll
            for (int q = 0; q < 4; q++) {
                float4 v = *reinterpret_cast<const float4*>(src + q * 4);
                uint2 hh, ll;
                split2(v.x, v.y, hh.x, ll.x);
                split2(v.z, v.w, hh.y, ll.y);
                *reinterpret_cast<uint2*>(dh + q * 8) = hh;
                *reinterpret_cast<uint2*>(dl + q * 8) = ll;
            }
        }
        CP_WAIT0();
        __syncthreads();
#pragma unroll
        for (int k16 = 0; k16 < 4; k16++) {
            const int kk = k16 * 16;
            u32 bh[8], bl[8];
            ldsm4t(bh[0], bh[1], bh[2], bh[3],
                   sbase + TL_BH + ((kk + lr) * 136 + ncol0 + lc) * 2);
            ldsm4t(bh[4], bh[5], bh[6], bh[7],
                   sbase + TL_BH + ((kk + lr) * 136 + ncol0 + 16 + lc) * 2);
            ldsm4t(bl[0], bl[1], bl[2], bl[3],
                   sbase + TL_BL + ((kk + lr) * 136 + ncol0 + lc) * 2);
            ldsm4t(bl[4], bl[5], bl[6], bl[7],
                   sbase + TL_BL + ((kk + lr) * 136 + ncol0 + 16 + lc) * 2);
#pragma unroll
            for (int mt = 0; mt < 2; mt++) {
                u32 ah[4], al[4];
                ldsm4(ah[0], ah[1], ah[2], ah[3],
                      sbase + TL_AH + ((mrow0 + mt * 16 + lr) * 72 + kk + lc) * 2);
                ldsm4(al[0], al[1], al[2], al[3],
                      sbase + TL_AL + ((mrow0 + mt * 16 + lr) * 72 + kk + lc) * 2);
#pragma unroll
                for (int nt = 0; nt < 4; nt++) {
                    mma16816(acc[mt][nt], ah, &bh[nt * 2]);
                    mma16816(acc[mt][nt], ah, &bl[nt * 2]);
                    mma16816(acc[mt][nt], al, &bh[nt * 2]);
                }
            }
        }
        __syncthreads();
    }

    // h1 epilogue
#pragma unroll
    for (int mt = 0; mt < 2; mt++) {
#pragma unroll
        for (int nt = 0; nt < 4; nt++) {
            int r = mrow0 + mt * 16 + g;
            int cl = ncol0 + nt * 8 + t * 2;
            float b0v = b1s[cl], b1v = b1s[cl + 1];
            u32 hh, ll;
            split2(fmaxf(acc[mt][nt][0] + b0v, 0.f),
                   fmaxf(acc[mt][nt][1] + b1v, 0.f), hh, ll);
            *reinterpret_cast<u32*>(smem + TL_H1H + r * 272 + cl * 2) = hh;
            *reinterpret_cast<u32*>(smem + TL_H1L + r * 272 + cl * 2) = ll;
            split2(fmaxf(acc[mt][nt][2] + b0v, 0.f),
                   fmaxf(acc[mt][nt][3] + b1v, 0.f), hh, ll);
            *reinterpret_cast<u32*>(smem + TL_H1H + (r + 8) * 272 + cl * 2) = hh;
            *reinterpret_cast<u32*>(smem + TL_H1L + (r + 8) * 272 + cl * 2) = ll;
        }
    }

    // ---- Phase 2: h2 = relu(h1 @ Wc2 + bc2), K = 128 ----
#pragma unroll
    for (int mt = 0; mt < 2; mt++)
#pragma unroll
        for (int nt = 0; nt < 4; nt++)
#pragma unroll
            for (int r = 0; r < 4; r++) acc[mt][nt][r] = 0.f;

    for (int c = 0; c < 2; c++) {
        const int k0 = c * 64;
        if (c == 1) {
            tail_cpB(sbase, TL_B2H, TL_B2L, g_Wc2h, g_Wc2l, k0);
            CP_COMMIT();
        }
        CP_WAIT0();
        __syncthreads();
#pragma unroll
        for (int k16 = 0; k16 < 4; k16++) {
            const int kk = k16 * 16;
            u32 bh[8], bl[8];
            ldsm4t(bh[0], bh[1], bh[2], bh[3],
                   sbase + TL_B2H + ((kk + lr) * 136 + ncol0 + lc) * 2);
            ldsm4t(bh[4], bh[5], bh[6], bh[7],
                   sbase + TL_B2H + ((kk + lr) * 136 + ncol0 + 16 + lc) * 2);
            ldsm4t(bl[0], bl[1], bl[2], bl[3],
                   sbase + TL_B2L + ((kk + lr) * 136 + ncol0 + lc) * 2);
            ldsm4t(bl[4], bl[5], bl[6], bl[7],
                   sbase + TL_B2L + ((kk + lr) * 136 + ncol0 + 16 + lc) * 2);
#pragma unroll
            for (int mt = 0; mt < 2; mt++) {
                u32 ah[4], al[4];
                ldsm4(ah[0], ah[1], ah[2], ah[3],
                      sbase + TL_H1H + ((mrow0 + mt * 16 + lr) * 136 + k0 + kk + lc) * 2);
                ldsm4(al[0], al[1], al[2], al[3],
                      sbase + TL_H1L + ((mrow0 + mt * 16 + lr) * 136 + k0 + kk + lc) * 2);
#pragma unroll
                for (int nt = 0; nt < 4; nt++) {
                    mma16816(acc[mt][nt], ah, &bh[nt * 2]);
                    mma16816(acc[mt][nt], ah, &bl[nt * 2]);
                    mma16816(acc[mt][nt], al, &bh[nt * 2]);
                }
            }
        }
        __syncthreads();
    }

    // ---- head ----
    {
        float ph[4][2];
#pragma unroll
        for (int i = 0; i < 4; i++) { ph[i][0] = 0.f; ph[i][1] = 0.f; }
#pragma unroll
        for (int mt = 0; mt < 2; mt++) {
#pragma unroll
            for (int nt = 0; nt < 4; nt++) {
                int cl = ncol0 + nt * 8 + t * 2;
                float b0v = b2s[cl], b1v = b2s[cl + 1];
                float w00 = W3s[cl * 2], w01 = W3s[cl * 2 + 1];
                float w10 = W3s[(cl + 1) * 2], w11 = W3s[(cl + 1) * 2 + 1];
                float h0 = fmaxf(acc[mt][nt][0] + b0v, 0.f);
                float h1 = fmaxf(acc[mt][nt][1] + b1v, 0.f);
                ph[mt * 2][0] = fmaf(h0, w00, fmaf(h1, w10, ph[mt * 2][0]));
                ph[mt * 2][1] = fmaf(h0, w01, fmaf(h1, w11, ph[mt * 2][1]));
                h0 = fmaxf(acc[mt][nt][2] + b0v, 0.f);
                h1 = fmaxf(acc[mt][nt][3] + b1v, 0.f);
                ph[mt * 2 + 1][0] = fmaf(h0, w00, fmaf(h1, w10, ph[mt * 2 + 1][0]));
                ph[mt * 2 + 1][1] = fmaf(h0, w01, fmaf(h1, w11, ph[mt * 2 + 1][1]));
            }
        }
#pragma unroll
        for (int i = 0; i < 4; i++) {
#pragma unroll
            for (int a = 0; a < 2; a++) {
                ph[i][a] += __shfl_xor_sync(0xffffffffu, ph[i][a], 1);
                ph[i][a] += __shfl_xor_sync(0xffffffffu, ph[i][a], 2);
            }
        }
        if (t == 0) {
#pragma unroll
            for (int i = 0; i < 4; i++) {
                int row = mrow0 + (i >> 1) * 16 + (i & 1) * 8 + g;
                pt[row * 8 + nwarp * 2 + 0] = ph[i][0];
                pt[row * 8 + nwarp * 2 + 1] = ph[i][1];
            }
        }
    }
    __syncthreads();
    if (tid < 128) {
        int row = tid >> 1, a = tid & 1;
        float s = pt[row * 8 + a] + pt[row * 8 + 2 + a] +
                  pt[row * 8 + 4 + a] + pt[row * 8 + 6 + a];
        out[(size_t)(row0 + row) * 2 + a] = tanhf(s + b3s[a]);
    }
}

// ---------------------------------------------------------------------------
// kernel_launch
// ---------------------------------------------------------------------------
extern "C" void kernel_launch(void* const* d_in, const int* in_sizes, int n_in,
                              void* d_out, int out_size) {
    const float* S0  = (const float*)d_in[0];
    const float* S1  = (const float*)d_in[1];
    const float* S2  = (const float*)d_in[2];
    const float* W0  = (const float*)d_in[3];
    const float* b0  = (const float*)d_in[4];
    const float* Wg  = (const float*)d_in[5];
    const float* bg  = (const float*)d_in[6];
    const float* Ws1 = (const float*)d_in[7];
    const float* bs1 = (const float*)d_in[8];
    const float* Ws2 = (const float*)d_in[9];
    const float* bs2 = (const float*)d_in[10];
    const float* Wq  = (const float*)d_in[11];
    const float* Wk  = (const float*)d_in[12];
    const float* Wv  = (const float*)d_in[13];
    const float* Wc1 = (const float*)d_in[14];
    const float* bc1 = (const float*)d_in[15];
    const float* Wc2 = (const float*)d_in[16];
    const float* bc2 = (const float*)d_in[17];
    const float* Wc3 = (const float*)d_in[18];
    const float* bc3 = (const float*)d_in[19];
    float* out = (float*)d_out;

    void* p;
    cudaGetSymbolAddress(&p, g_concat); float* C = (float*)p;

    cudaFuncSetAttribute(k_attn5, cudaFuncAttributeMaxDynamicSharedMemorySize,
                         ATTN_SMEM_BYTES);
    cudaFuncSetAttribute(k1_gemm, cudaFuncAttributeMaxDynamicSharedMemorySize,
                         K1_SMEM_BYTES);
    cudaFuncSetAttribute(k_tail, cudaFuncAttributeMaxDynamicSharedMemorySize,
                         TAIL_SMEM_BYTES);

    // K0: split all weights (+ M = Wq@Wk^T)
    k_split<<<464, 256>>>(Wg, Wc1, Wc2, Ws2, Wv, Wq, Wk);
    // K1: env_e -> g_concat[:,64:128]  (64-row tiles, 3 CTA/SM)
    k1_gemm<<<B_TOT / 64, 256, K1_SMEM_BYTES>>>(S1, bg, C);
    // K2: own_e + attention -> g_concat[:,0:64], [:,128:192]
    k_attn5<<<B_TOT / 16, 256, ATTN_SMEM_BYTES>>>(S0, S2, W0, b0, Ws1, bs1, bs2);
    // K3: fused tail -> out
    k_tail<<<B_TOT / 64, 256, TAIL_SMEM_BYTES>>>(bc1, bc2, Wc3, bc3, out);
}